// round 5
// baseline (speedup 1.0000x reference)
#include <cuda_runtime.h>

// Problem constants (match reference_code)
#define KS   17
#define HP   256
#define WP   256
#define HI   (HP + KS - 1)   // 272
#define WI   (WP + KS - 1)   // 272
#define P    (HP * WP)       // 65536
#define IMG_BC_STRIDE (HI * WI)  // 73984 floats per (b,c) plane

// Tiling:
//   thread: 4 consecutive x-pixels x 2 (b,c) planes
//   block : (16,2,6) = 192 threads -> tile 64x2 px, all 12 bc
//   grid  : (4,128) = 512 blocks
// Inner loop restructured for MLP: per kh, ALL 17 kern float4 are loaded into
// a register array BEFORE any FFMA consumes them -> 17 independent DRAM lines
// in flight per warp (vs ~3 in round 3, which capped HBM at 2.2 TB/s).
// __launch_bounds__(192,2) gives ptxas ~170 regs so the batch stays live.

__global__ void __launch_bounds__(192, 2)
blur_kernel(const float* __restrict__ img,
            const float* __restrict__ kernels,
            const int*   __restrict__ idx_p,
            float*       __restrict__ out)
{
    const int x0  = blockIdx.x * 64 + threadIdx.x * 4;  // multiple of 4
    const int y   = blockIdx.y * 2 + threadIdx.y;
    const int bc0 = threadIdx.z * 2;                    // 0,2,...,10
    const int p0  = y * WP + x0;

    const long long kidx = (long long)(*idx_p);
    const float* __restrict__ kern =
        kernels + kidx * (long long)(KS * KS) * (long long)P;

    float acc[2][4];
#pragma unroll
    for (int bc = 0; bc < 2; bc++)
#pragma unroll
        for (int r = 0; r < 4; r++) acc[bc][r] = 0.0f;

#pragma unroll 1
    for (int kh = 0; kh < KS; kh++) {
        const float* __restrict__ irow =
            img + (long long)bc0 * IMG_BC_STRIDE + (long long)(y + kh) * WI + x0;
        const float4* __restrict__ krow =
            (const float4*)(kern + (long long)kh * KS * P + p0);

        // ---- batched loads: 10 img float4 (L2-resident) ----
        float win[2][20];
#pragma unroll
        for (int bc = 0; bc < 2; bc++) {
#pragma unroll
            for (int v = 0; v < 5; v++) {
                const float4 t = *(const float4*)(irow + bc * IMG_BC_STRIDE + v * 4);
                win[bc][v * 4 + 0] = t.x;
                win[bc][v * 4 + 1] = t.y;
                win[bc][v * 4 + 2] = t.z;
                win[bc][v * 4 + 3] = t.w;
            }
        }

        // ---- batched loads: ALL 17 kern float4 (independent DRAM lines) ----
        float4 w[KS];
#pragma unroll
        for (int kw = 0; kw < KS; kw++)
            w[kw] = krow[(long long)kw * (P / 4)];

        // ---- compute: 17 x 2bc x 4px FFMAs ----
#pragma unroll
        for (int kw = 0; kw < KS; kw++) {
#pragma unroll
            for (int bc = 0; bc < 2; bc++) {
                acc[bc][0] = fmaf(w[kw].x, win[bc][kw + 0], acc[bc][0]);
                acc[bc][1] = fmaf(w[kw].y, win[bc][kw + 1], acc[bc][1]);
                acc[bc][2] = fmaf(w[kw].z, win[bc][kw + 2], acc[bc][2]);
                acc[bc][3] = fmaf(w[kw].w, win[bc][kw + 3], acc[bc][3]);
            }
        }
    }

#pragma unroll
    for (int bc = 0; bc < 2; bc++) {
        *(float4*)(out + (long long)(bc0 + bc) * P + p0) =
            make_float4(acc[bc][0], acc[bc][1], acc[bc][2], acc[bc][3]);
    }
}

extern "C" void kernel_launch(void* const* d_in, const int* in_sizes, int n_in,
                              void* d_out, int out_size)
{
    const float* img     = (const float*)d_in[0];  // (4,3,272,272) f32
    const float* kernels = (const float*)d_in[1];  // (16,1,289,65536) f32
    const int*   idx     = (const int*)d_in[2];    // scalar int32
    float*       out     = (float*)d_out;          // (4,3,256,256) f32

    dim3 block(16, 2, 6);
    dim3 grid(WP / 64, HP / 2);   // (4, 128)
    blur_kernel<<<grid, block>>>(img, kernels, idx, out);
}

// round 6
// speedup vs baseline: 1.2685x; 1.2685x over previous
#include <cuda_runtime.h>
#include <cstdint>

// Problem constants
#define KS   17
#define HP   256
#define WP   256
#define HI   (HP + KS - 1)   // 272
#define WI   (WP + KS - 1)   // 272
#define P    (HP * WP)       // 65536
#define IMG_BC_STRIDE (HI * WI)

// Tiling: block = 128 consecutive px of ONE row x all 12 bc.
//   threads: (32,4) = 128; thread = 4 px (tx) x 3 bc (ty)
//   grid   : (2,256) = 512 blocks
// kern weights for a tap (kh,kw) over the block's 128 px are a CONTIGUOUS
// 512B chunk -> fetched with cp.async.bulk (TMA path, L2->SMEM, bypasses the
// per-SM L1tex miss-tracking cap that pinned rounds 2-5 at ~2.2 TB/s).
#define TILE_X       128
#define NSTAGE       3
#define CHUNK_BYTES  (TILE_X * 4)        // 512
#define STAGE_FLOATS (KS * TILE_X)       // 2176
#define STAGE_BYTES  (STAGE_FLOATS * 4)  // 8704
#define NTHREADS     128

__device__ __forceinline__ void mbar_init(uint32_t a, uint32_t cnt) {
    asm volatile("mbarrier.init.shared.b64 [%0], %1;" :: "r"(a), "r"(cnt) : "memory");
}
__device__ __forceinline__ void mbar_expect_tx(uint32_t a, uint32_t bytes) {
    asm volatile("mbarrier.arrive.expect_tx.shared.b64 _, [%0], %1;"
                 :: "r"(a), "r"(bytes) : "memory");
}
__device__ __forceinline__ void mbar_wait(uint32_t a, uint32_t parity) {
    asm volatile(
        "{\n\t"
        ".reg .pred p;\n\t"
        "WAIT_%=: mbarrier.try_wait.parity.acquire.cta.shared::cta.b64 p, [%0], %1, 0x989680;\n\t"
        "@p bra.uni DONE_%=;\n\t"
        "bra.uni WAIT_%=;\n\t"
        "DONE_%=:\n\t"
        "}"
        :: "r"(a), "r"(parity) : "memory");
}
__device__ __forceinline__ void bulk_g2s(uint32_t dst, const void* src,
                                         uint32_t bytes, uint32_t bar) {
    asm volatile(
        "cp.async.bulk.shared::cta.global.mbarrier::complete_tx::bytes [%0], [%1], %2, [%3];"
        :: "r"(dst), "l"(src), "r"(bytes), "r"(bar) : "memory");
}

__global__ void __launch_bounds__(NTHREADS, 4)
blur_kernel(const float* __restrict__ img,
            const float* __restrict__ kernels,
            const int*   __restrict__ idx_p,
            float*       __restrict__ out)
{
    __shared__ __align__(16) float    skern[NSTAGE * STAGE_FLOATS];
    __shared__ __align__(8)  uint64_t fullbar[NSTAGE];

    const int tx  = threadIdx.x;          // 0..31 -> 4 px each
    const int ty  = threadIdx.y;          // 0..3  -> 3 bc each
    const int tid = tx + ty * 32;

    const int xblk = blockIdx.x * TILE_X;
    const int y0   = blockIdx.y;
    const int xt   = xblk + tx * 4;
    const int bc0  = ty * 3;
    const int p0   = y0 * WP + xt;

    const long long kidx = (long long)(*idx_p);
    // kern chunk base for this block: tap t, pixels [p_base, p_base+128)
    const float* __restrict__ kern_blk =
        kernels + kidx * (long long)(KS * KS) * (long long)P
                + (long long)y0 * WP + xblk;

    const uint32_t sker = (uint32_t)__cvta_generic_to_shared(skern);
    const uint32_t sbar = (uint32_t)__cvta_generic_to_shared(fullbar);

    if (tid == 0) {
#pragma unroll
        for (int s = 0; s < NSTAGE; s++) mbar_init(sbar + s * 8, 1);
    }
    asm volatile("fence.proxy.async.shared::cta;" ::: "memory");
    __syncthreads();

    // issue one stage: all 17 tap-chunks of row kh
    auto issue_stage = [&](int s, int kh) {
        const uint32_t bar = sbar + s * 8;
        mbar_expect_tx(bar, STAGE_BYTES);
        const uint32_t dst0 = sker + (uint32_t)(s * STAGE_BYTES);
#pragma unroll
        for (int kw = 0; kw < KS; kw++) {
            bulk_g2s(dst0 + kw * CHUNK_BYTES,
                     kern_blk + (long long)(kh * KS + kw) * P,
                     CHUNK_BYTES, bar);
        }
    };

    if (tid == 0) {
        issue_stage(0, 0);
        issue_stage(1, 1);
        issue_stage(2, 2);
    }

    float acc[3][4];
#pragma unroll
    for (int bc = 0; bc < 3; bc++)
#pragma unroll
        for (int r = 0; r < 4; r++) acc[bc][r] = 0.0f;

#pragma unroll 1
    for (int kh = 0; kh < KS; kh++) {
        const int s  = kh % NSTAGE;
        const int ph = (kh / NSTAGE) & 1;

        // img window: 20 floats per bc as 5 x LDG.128 (img is L2-resident)
        const float* __restrict__ irow =
            img + (long long)bc0 * IMG_BC_STRIDE + (long long)(y0 + kh) * WI + xt;
        float win[3][20];
#pragma unroll
        for (int bc = 0; bc < 3; bc++) {
#pragma unroll
            for (int v = 0; v < 5; v++) {
                const float4 t = *(const float4*)(irow + bc * IMG_BC_STRIDE + v * 4);
                win[bc][v * 4 + 0] = t.x;
                win[bc][v * 4 + 1] = t.y;
                win[bc][v * 4 + 2] = t.z;
                win[bc][v * 4 + 3] = t.w;
            }
        }

        mbar_wait(sbar + s * 8, (uint32_t)ph);

        const float* __restrict__ srow = skern + s * STAGE_FLOATS + tx * 4;
#pragma unroll
        for (int kw = 0; kw < KS; kw++) {
            const float4 w = *(const float4*)(srow + kw * TILE_X);
#pragma unroll
            for (int bc = 0; bc < 3; bc++) {
                acc[bc][0] = fmaf(w.x, win[bc][kw + 0], acc[bc][0]);
                acc[bc][1] = fmaf(w.y, win[bc][kw + 1], acc[bc][1]);
                acc[bc][2] = fmaf(w.z, win[bc][kw + 2], acc[bc][2]);
                acc[bc][3] = fmaf(w.w, win[bc][kw + 3], acc[bc][3]);
            }
        }

        __syncthreads();   // all warps done reading stage s before refill

        if (tid == 0 && kh + NSTAGE < KS)
            issue_stage(s, kh + NSTAGE);
    }

#pragma unroll
    for (int bc = 0; bc < 3; bc++) {
        *(float4*)(out + (long long)(bc0 + bc) * P + p0) =
            make_float4(acc[bc][0], acc[bc][1], acc[bc][2], acc[bc][3]);
    }
}

extern "C" void kernel_launch(void* const* d_in, const int* in_sizes, int n_in,
                              void* d_out, int out_size)
{
    const float* img     = (const float*)d_in[0];  // (4,3,272,272) f32
    const float* kernels = (const float*)d_in[1];  // (16,1,289,65536) f32
    const int*   idx     = (const int*)d_in[2];    // scalar int32
    float*       out     = (float*)d_out;          // (4,3,256,256) f32

    dim3 block(32, 4);                  // 128 threads
    dim3 grid(WP / TILE_X, HP);         // (2,256) = 512 blocks
    blur_kernel<<<grid, block>>>(img, kernels, idx, out);
}

// round 7
// speedup vs baseline: 1.2810x; 1.0099x over previous
#include <cuda_runtime.h>
#include <cstdint>

// Problem constants
#define KS   17
#define HP   256
#define WP   256
#define HI   (HP + KS - 1)   // 272
#define WI   (WP + KS - 1)   // 272
#define P    (HP * WP)       // 65536
#define IMG_BC_STRIDE (HI * WI)

// Tiling: block = 128 consecutive px of ONE row x 6 bc (half of 12).
//   threads: (32,3) = 96; thread = 4 px x 2 bc
//   grid   : (2,256,2) = 1024 blocks (z = bc half) -> ~7 blocks/SM, ONE wave
// kern weights per tap = contiguous 512B chunk, fetched via cp.async.bulk
// (TMA path). bc-half blocks duplicate kern fetches but hit L2 (slice is
// L2-resident) -> DRAM still sees kern exactly once.
#define TILE_X       128
#define NSTAGE       3
#define CHUNK_BYTES  (TILE_X * 4)        // 512
#define STAGE_FLOATS (KS * TILE_X)       // 2176
#define STAGE_BYTES  (STAGE_FLOATS * 4)  // 8704
#define NTHREADS     96

__device__ __forceinline__ void mbar_init(uint32_t a, uint32_t cnt) {
    asm volatile("mbarrier.init.shared.b64 [%0], %1;" :: "r"(a), "r"(cnt) : "memory");
}
__device__ __forceinline__ void mbar_expect_tx(uint32_t a, uint32_t bytes) {
    asm volatile("mbarrier.arrive.expect_tx.shared.b64 _, [%0], %1;"
                 :: "r"(a), "r"(bytes) : "memory");
}
__device__ __forceinline__ void mbar_wait(uint32_t a, uint32_t parity) {
    asm volatile(
        "{\n\t"
        ".reg .pred p;\n\t"
        "WAIT_%=: mbarrier.try_wait.parity.acquire.cta.shared::cta.b64 p, [%0], %1, 0x989680;\n\t"
        "@p bra.uni DONE_%=;\n\t"
        "bra.uni WAIT_%=;\n\t"
        "DONE_%=:\n\t"
        "}"
        :: "r"(a), "r"(parity) : "memory");
}
__device__ __forceinline__ void bulk_g2s(uint32_t dst, const void* src,
                                         uint32_t bytes, uint32_t bar) {
    asm volatile(
        "cp.async.bulk.shared::cta.global.mbarrier::complete_tx::bytes [%0], [%1], %2, [%3];"
        :: "r"(dst), "l"(src), "r"(bytes), "r"(bar) : "memory");
}

__global__ void __launch_bounds__(NTHREADS, 8)
blur_kernel(const float* __restrict__ img,
            const float* __restrict__ kernels,
            const int*   __restrict__ idx_p,
            float*       __restrict__ out)
{
    __shared__ __align__(16) float    skern[NSTAGE * STAGE_FLOATS];
    __shared__ __align__(8)  uint64_t fullbar[NSTAGE];

    const int tx  = threadIdx.x;          // 0..31 -> 4 px each
    const int ty  = threadIdx.y;          // 0..2  -> 2 bc each
    const int tid = tx + ty * 32;

    const int xblk = blockIdx.x * TILE_X;
    const int y0   = blockIdx.y;
    const int xt   = xblk + tx * 4;
    const int bc0  = blockIdx.z * 6 + ty * 2;
    const int p0   = y0 * WP + xt;

    const long long kidx = (long long)(*idx_p);
    const float* __restrict__ kern_blk =
        kernels + kidx * (long long)(KS * KS) * (long long)P
                + (long long)y0 * WP + xblk;

    const uint32_t sker = (uint32_t)__cvta_generic_to_shared(skern);
    const uint32_t sbar = (uint32_t)__cvta_generic_to_shared(fullbar);

    if (tid == 0) {
#pragma unroll
        for (int s = 0; s < NSTAGE; s++) mbar_init(sbar + s * 8, 1);
    }
    asm volatile("fence.proxy.async.shared::cta;" ::: "memory");
    __syncthreads();

    auto issue_stage = [&](int s, int kh) {
        const uint32_t bar = sbar + s * 8;
        mbar_expect_tx(bar, STAGE_BYTES);
        const uint32_t dst0 = sker + (uint32_t)(s * STAGE_BYTES);
#pragma unroll
        for (int kw = 0; kw < KS; kw++) {
            bulk_g2s(dst0 + kw * CHUNK_BYTES,
                     kern_blk + (long long)(kh * KS + kw) * P,
                     CHUNK_BYTES, bar);
        }
    };

    if (tid == 0) {
        issue_stage(0, 0);
        issue_stage(1, 1);
        issue_stage(2, 2);
    }

    float acc[2][4];
#pragma unroll
    for (int bc = 0; bc < 2; bc++)
#pragma unroll
        for (int r = 0; r < 4; r++) acc[bc][r] = 0.0f;

#pragma unroll 1
    for (int kh = 0; kh < KS; kh++) {
        const int s  = kh % NSTAGE;
        const int ph = (kh / NSTAGE) & 1;

        // img window: 20 floats per bc as 5 x LDG.128 (img is L2-resident)
        const float* __restrict__ irow =
            img + (long long)bc0 * IMG_BC_STRIDE + (long long)(y0 + kh) * WI + xt;
        float win[2][20];
#pragma unroll
        for (int bc = 0; bc < 2; bc++) {
#pragma unroll
            for (int v = 0; v < 5; v++) {
                const float4 t = *(const float4*)(irow + bc * IMG_BC_STRIDE + v * 4);
                win[bc][v * 4 + 0] = t.x;
                win[bc][v * 4 + 1] = t.y;
                win[bc][v * 4 + 2] = t.z;
                win[bc][v * 4 + 3] = t.w;
            }
        }

        mbar_wait(sbar + s * 8, (uint32_t)ph);

        const float* __restrict__ srow = skern + s * STAGE_FLOATS + tx * 4;
#pragma unroll
        for (int kw = 0; kw < KS; kw++) {
            const float4 w = *(const float4*)(srow + kw * TILE_X);
#pragma unroll
            for (int bc = 0; bc < 2; bc++) {
                acc[bc][0] = fmaf(w.x, win[bc][kw + 0], acc[bc][0]);
                acc[bc][1] = fmaf(w.y, win[bc][kw + 1], acc[bc][1]);
                acc[bc][2] = fmaf(w.z, win[bc][kw + 2], acc[bc][2]);
                acc[bc][3] = fmaf(w.w, win[bc][kw + 3], acc[bc][3]);
            }
        }

        __syncthreads();   // all warps done reading stage s before refill

        if (tid == 0 && kh + NSTAGE < KS)
            issue_stage(s, kh + NSTAGE);
    }

#pragma unroll
    for (int bc = 0; bc < 2; bc++) {
        *(float4*)(out + (long long)(bc0 + bc) * P + p0) =
            make_float4(acc[bc][0], acc[bc][1], acc[bc][2], acc[bc][3]);
    }
}

extern "C" void kernel_launch(void* const* d_in, const int* in_sizes, int n_in,
                              void* d_out, int out_size)
{
    const float* img     = (const float*)d_in[0];  // (4,3,272,272) f32
    const float* kernels = (const float*)d_in[1];  // (16,1,289,65536) f32
    const int*   idx     = (const int*)d_in[2];    // scalar int32
    float*       out     = (float*)d_out;          // (4,3,256,256) f32

    dim3 block(32, 3);                    // 96 threads
    dim3 grid(WP / TILE_X, HP, 2);        // (2,256,2) = 1024 blocks
    blur_kernel<<<grid, block>>>(img, kernels, idx, out);
}